// round 16
// baseline (speedup 1.0000x reference)
#include <cuda_runtime.h>
#include <cuda_bf16.h>

typedef unsigned long long ull;

// ---------------- problem constants ----------------
#define TT 512
#define BB 32
#define HH 512
#define GM 16384          // T*B
#define GN 4096           // 2 dirs * 4H
#define GK 512            // D (= H)

// ---------------- scratch ----------------
__device__ float g_xpre[(size_t)GM * GN];   // precomputed input gates (+ both biases)
__device__ unsigned int g_flag[2][64];      // per-CTA step flags (barrier)

// ---------------- f32x2 helpers ----------------
__device__ __forceinline__ ull pack2(float lo, float hi) {
    ull r; asm("mov.b64 %0, {%1, %2};" : "=l"(r) : "f"(lo), "f"(hi)); return r;
}
__device__ __forceinline__ void unpack2(ull v, float& lo, float& hi) {
    asm("mov.b64 {%0, %1}, %2;" : "=f"(lo), "=f"(hi) : "l"(v));
}
__device__ __forceinline__ ull fma2(ull a, ull b, ull c) {
    ull d; asm("fma.rn.f32x2 %0, %1, %2, %3;" : "=l"(d) : "l"(a), "l"(b), "l"(c)); return d;
}
__device__ __forceinline__ ull add2(ull a, ull b) {
    ull d; asm("add.rn.f32x2 %0, %1, %2;" : "=l"(d) : "l"(a), "l"(b)); return d;
}

// ---------------- fast activations ----------------
__device__ __forceinline__ float tanh_fast(float x) {
    float y; asm("tanh.approx.f32 %0, %1;" : "=f"(y) : "f"(x)); return y;
}
__device__ __forceinline__ float sigmoid_fast(float x) {
    return fmaf(tanh_fast(0.5f * x), 0.5f, 0.5f);
}

// ---------------- release/acquire flag ops ----------------
__device__ __forceinline__ void st_rel(unsigned* p, unsigned v) {
    asm volatile("st.release.gpu.global.u32 [%0], %1;" :: "l"(p), "r"(v) : "memory");
}
__device__ __forceinline__ void ld_acq2(const unsigned* p, unsigned& a, unsigned& b) {
    asm volatile("ld.acquire.gpu.global.v2.u32 {%0,%1}, [%2];"
                 : "=r"(a), "=r"(b) : "l"(p) : "memory");
}

// ============================================================
// Kernel 1: x_pre GEMM.  C[m][n] = A[m][:] . W[n][:] + bih[n] + bhh[n]
// (unchanged — known good)
// ============================================================
#define BM 128
#define BN 128
#define BK 16

__global__ void __launch_bounds__(256, 2) gemm_xpre(
    const float* __restrict__ A, const float* __restrict__ W,
    const float* __restrict__ bih, const float* __restrict__ bhh)
{
    // reset barrier flags (graph replays reuse device globals)
    if (blockIdx.x == 0 && blockIdx.y == 0 && threadIdx.x < 128) {
        ((unsigned*)g_flag)[threadIdx.x] = 0u;
    }

    __shared__ float As[2][BK][BM];
    __shared__ float Bs[2][BK][BN];

    const int tid = threadIdx.x;
    const int m0 = blockIdx.y * BM;
    const int n0 = blockIdx.x * BN;

    const int lr = tid >> 2;           // 0..63
    const int lk = (tid & 3) << 2;     // 0,4,8,12
    const int lk4 = tid & 3;

    const float4* A4 = (const float4*)A;
    const float4* W4 = (const float4*)W;

    const int ty = tid >> 4;
    const int tx = tid & 15;

    ull acc[8][4];
#pragma unroll
    for (int i = 0; i < 8; i++)
#pragma unroll
        for (int j = 0; j < 4; j++) acc[i][j] = 0ull;

    {
        int ak = lk4;
        float4 a0 = A4[(size_t)(m0 + lr) * 128 + ak];
        float4 a1 = A4[(size_t)(m0 + lr + 64) * 128 + ak];
        float4 b0 = W4[(size_t)(n0 + lr) * 128 + ak];
        float4 b1 = W4[(size_t)(n0 + lr + 64) * 128 + ak];
        As[0][lk + 0][lr] = a0.x; As[0][lk + 1][lr] = a0.y;
        As[0][lk + 2][lr] = a0.z; As[0][lk + 3][lr] = a0.w;
        As[0][lk + 0][lr + 64] = a1.x; As[0][lk + 1][lr + 64] = a1.y;
        As[0][lk + 2][lr + 64] = a1.z; As[0][lk + 3][lr + 64] = a1.w;
        Bs[0][lk + 0][lr] = b0.x; Bs[0][lk + 1][lr] = b0.y;
        Bs[0][lk + 2][lr] = b0.z; Bs[0][lk + 3][lr] = b0.w;
        Bs[0][lk + 0][lr + 64] = b1.x; Bs[0][lk + 1][lr + 64] = b1.y;
        Bs[0][lk + 2][lr + 64] = b1.z; Bs[0][lk + 3][lr + 64] = b1.w;
    }
    __syncthreads();

    int bf = 0;
    const int NKT = GK / BK;
    float4 ra0, ra1, rb0, rb1;

    for (int kt = 0; kt < NKT; kt++) {
        if (kt < NKT - 1) {
            int ak = (kt + 1) * 4 + lk4;
            ra0 = A4[(size_t)(m0 + lr) * 128 + ak];
            ra1 = A4[(size_t)(m0 + lr + 64) * 128 + ak];
            rb0 = W4[(size_t)(n0 + lr) * 128 + ak];
            rb1 = W4[(size_t)(n0 + lr + 64) * 128 + ak];
        }
#pragma unroll
        for (int k = 0; k < BK; k++) {
            float4 a0 = *(const float4*)&As[bf][k][ty * 8];
            float4 a1 = *(const float4*)&As[bf][k][ty * 8 + 4];
            ulonglong2 bA = *(const ulonglong2*)&Bs[bf][k][tx * 8];
            ulonglong2 bB = *(const ulonglong2*)&Bs[bf][k][tx * 8 + 4];
            ull bb0 = bA.x, bb1 = bA.y, bb2 = bB.x, bb3 = bB.y;
            float av[8] = {a0.x, a0.y, a0.z, a0.w, a1.x, a1.y, a1.z, a1.w};
#pragma unroll
            for (int i = 0; i < 8; i++) {
                ull ap = pack2(av[i], av[i]);
                acc[i][0] = fma2(ap, bb0, acc[i][0]);
                acc[i][1] = fma2(ap, bb1, acc[i][1]);
                acc[i][2] = fma2(ap, bb2, acc[i][2]);
                acc[i][3] = fma2(ap, bb3, acc[i][3]);
            }
        }
        if (kt < NKT - 1) {
            int nb = bf ^ 1;
            As[nb][lk + 0][lr] = ra0.x; As[nb][lk + 1][lr] = ra0.y;
            As[nb][lk + 2][lr] = ra0.z; As[nb][lk + 3][lr] = ra0.w;
            As[nb][lk + 0][lr + 64] = ra1.x; As[nb][lk + 1][lr + 64] = ra1.y;
            As[nb][lk + 2][lr + 64] = ra1.z; As[nb][lk + 3][lr + 64] = ra1.w;
            Bs[nb][lk + 0][lr] = rb0.x; Bs[nb][lk + 1][lr] = rb0.y;
            Bs[nb][lk + 2][lr] = rb0.z; Bs[nb][lk + 3][lr] = rb0.w;
            Bs[nb][lk + 0][lr + 64] = rb1.x; Bs[nb][lk + 1][lr + 64] = rb1.y;
            Bs[nb][lk + 2][lr + 64] = rb1.z; Bs[nb][lk + 3][lr + 64] = rb1.w;
            __syncthreads();
            bf = nb;
        }
    }

    float bias[8];
#pragma unroll
    for (int j = 0; j < 8; j++) {
        int n = n0 + tx * 8 + j;
        bias[j] = bih[n] + bhh[n];
    }
#pragma unroll
    for (int i = 0; i < 8; i++) {
        size_t m = (size_t)(m0 + ty * 8 + i);
        float4 v0, v1;
        unpack2(acc[i][0], v0.x, v0.y);
        unpack2(acc[i][1], v0.z, v0.w);
        unpack2(acc[i][2], v1.x, v1.y);
        unpack2(acc[i][3], v1.z, v1.w);
        v0.x += bias[0]; v0.y += bias[1]; v0.z += bias[2]; v0.w += bias[3];
        v1.x += bias[4]; v1.y += bias[5]; v1.z += bias[6]; v1.w += bias[7];
        *(float4*)&g_xpre[m * GN + n0 + tx * 8]     = v0;
        *(float4*)&g_xpre[m * GN + n0 + tx * 8 + 4] = v1;
    }
}

// ============================================================
// Kernel 2: persistent bidirectional LSTM recurrence.
// R14 structure (coalesced sHO writeback RESTORED) with:
//  - flag-array barrier: per-CTA release store + vectorized acquire poll
//  - tanh.approx.f32 activations (sigmoid via tanh identity)
// ============================================================
#define RT 512                               // threads in recurrence CTA
#define HT_P 516
#define OFF_W    0                           // 16384 floats
#define OFF_HT   16384                       // 16512 floats
#define OFF_PART (16384 + 32 * HT_P)         // 16384 floats ([32][16][32])
#define OFF_GI   (OFF_PART + 32 * 16 * 32)   // 1056 floats
#define OFF_HO   (OFF_GI + 32 * 33)          // 288 floats ([32][9])
#define REC_FLOATS (OFF_HO + 32 * 9)
#define REC_SMEM (REC_FLOATS * 4)            // ~202,496 bytes

__global__ void __launch_bounds__(RT, 1) lstm_rec(
    const float* __restrict__ h0, const float* __restrict__ c0,
    const float* __restrict__ Whh, float* __restrict__ out,
    int write_states)
{
    extern __shared__ float sm[];
    float* sW    = sm + OFF_W;      // [32][512]
    float* hT    = sm + OFF_HT;     // [32][516]
    float* sPart = sm + OFF_PART;   // [32][16][32]
    float* sGI   = sm + OFF_GI;     // [32][33]
    float* sHO   = sm + OFF_HO;     // [32][9]

    const int tid = threadIdx.x;
    const int cta = blockIdx.x;       // 0..127
    const int d = cta >> 6;           // direction
    const int cc = cta & 63;
    const int base = cc << 3;         // h index base (8 per CTA)
    const int w = tid >> 5;           // k-chunk (0..15)
    const int b = tid & 31;           // batch

    // ---- load this CTA's W_hh slice: rows r = gate*8 + hl ----
    const float4* W4 = (const float4*)Whh;
#pragma unroll
    for (int i = 0; i < 8; i++) {
        int idx = tid + i * RT;          // 0..4095
        int r = idx >> 7;
        int k4 = idx & 127;
        int grow = ((r >> 3) << 9) + base + (r & 7);     // gate*512 + base + hl
        ((float4*)sW)[r * 128 + k4] = W4[(size_t)(d * 2048 + grow) * 128 + k4];
    }

    // c carried by tid<256: thread (hl = tid>>5 in 0..7, b)
    float c = 0.f;
    if (tid < 256) c = c0[(size_t)d * BB * HH + (size_t)b * HH + base + (tid >> 5)];

    // ---- prologue: prefetch gate inputs for step 0 (coalesced) ----
    float gi[2];
    {
        int t0 = d ? (TT - 1) : 0;
#pragma unroll
        for (int i = 0; i < 2; i++) {
            int idx = tid + (i << 9);
            int bb2 = idx >> 5, g = (idx >> 3) & 3, wi = idx & 7;
            gi[i] = g_xpre[(size_t)(t0 * BB + bb2) * GN + d * 2048 + g * 512 + base + wi];
        }
    }
    __syncthreads();

    for (int s = 0; s < TT; s++) {
        const int t = d ? (TT - 1 - s) : s;

        // ---- (a) deposit prefetched gate inputs into sGI ----
#pragma unroll
        for (int i = 0; i < 2; i++) {
            int idx = tid + (i << 9);
            int bb2 = idx >> 5, g = (idx >> 3) & 3, wi = idx & 7;
            sGI[bb2 * 33 + g * 8 + wi] = gi[i];
        }

        // ---- (b) stage previous h into hT (coalesced LDG + conflict-free STS) ----
        {
            const float* hsrc;
            int hstr4;
            if (s == 0) { hsrc = h0 + (size_t)d * BB * HH; hstr4 = HH >> 2; }
            else {
                int tp = d ? (t + 1) : (t - 1);
                hsrc = out + (size_t)tp * BB * 1024 + d * HH;
                hstr4 = 1024 >> 2;
            }
            const float4* s4 = (const float4*)hsrc;
#pragma unroll
            for (int i = 0; i < 8; i++) {
                int idx = tid + (i << 9);       // 0..4095
                int bb2 = idx >> 7;             // batch row
                int kq  = idx & 127;            // float4 within row
                float4 v = s4[(size_t)bb2 * hstr4 + kq];
                *(float4*)&hT[bb2 * HT_P + (kq << 2)] = v;
            }
        }

        // ---- (c) prefetch gate inputs for NEXT step ----
        if (s < TT - 1) {
            int tn = d ? (TT - 2 - s) : (s + 1);
#pragma unroll
            for (int i = 0; i < 2; i++) {
                int idx = tid + (i << 9);
                int bb2 = idx >> 5, g = (idx >> 3) & 3, wi = idx & 7;
                gi[i] = g_xpre[(size_t)(tn * BB + bb2) * GN + d * 2048 + g * 512 + base + wi];
            }
        }
        __syncthreads();   // S1

        // ---- (e) compute: 32-float k-chunk per thread ----
        ulonglong2 h2[8];
        {
            const ulonglong2* hp = (const ulonglong2*)&hT[b * HT_P + (w << 5)];
#pragma unroll
            for (int q = 0; q < 8; q++) h2[q] = hp[q];
        }

#pragma unroll 2
        for (int j = 0; j < 32; j++) {
            const ulonglong2* wp = (const ulonglong2*)(sW + j * 512 + (w << 5));
            ull a0 = 0, a1 = 0, a2 = 0, a3 = 0;
#pragma unroll
            for (int q = 0; q < 8; q += 2) {
                ulonglong2 wv0 = wp[q];
                ulonglong2 wv1 = wp[q + 1];
                a0 = fma2(wv0.x, h2[q].x, a0);
                a1 = fma2(wv0.y, h2[q].y, a1);
                a2 = fma2(wv1.x, h2[q + 1].x, a2);
                a3 = fma2(wv1.y, h2[q + 1].y, a3);
            }
            ull aa = add2(add2(a0, a1), add2(a2, a3));
            float lo, hi;
            unpack2(aa, lo, hi);
            sPart[(j << 9) + (w << 5) + b] = lo + hi;
        }
        __syncthreads();   // S2

        // ---- (g) update phase: tid<256, thread (hl, b) ----
        if (tid < 256) {
            const int hl = tid >> 5;
            float g4[4];
#pragma unroll
            for (int g = 0; g < 4; g++) {
                int j = g * 8 + hl;
                const float* pp = sPart + (j << 9) + b;
                float s0 = 0.f, s1 = 0.f, s2 = 0.f, s3 = 0.f;
#pragma unroll
                for (int q = 0; q < 16; q += 4) {
                    s0 += pp[(q + 0) << 5];
                    s1 += pp[(q + 1) << 5];
                    s2 += pp[(q + 2) << 5];
                    s3 += pp[(q + 3) << 5];
                }
                g4[g] = (s0 + s1) + (s2 + s3) + sGI[b * 33 + g * 8 + hl];
            }

            float ig = sigmoid_fast(g4[0]);
            float fg = sigmoid_fast(g4[1]);
            float gg = tanh_fast(g4[2]);
            float og = sigmoid_fast(g4[3]);
            c = fg * c + ig * gg;
            float h = og * tanh_fast(c);
            sHO[b * 9 + hl] = h;
        }
        __syncthreads();   // S3

        // ---- (j) coalesced h writeback (tid<256) ----
        if (tid < 256) {
            int bb2 = tid >> 3, wi = tid & 7;
            out[(size_t)t * BB * 1024 + (size_t)bb2 * 1024 + d * HH + base + wi] =
                sHO[bb2 * 9 + wi];
        }

        // ---- (k) per-direction flag barrier ----
        if (s < TT - 1) {
            __syncthreads();   // S4: all writeback STGs happen-before tid0's release
            if (tid == 0) st_rel(&g_flag[d][cc], (unsigned)(s + 1));
            if (tid < 32) {
                const unsigned tgt = (unsigned)(s + 1);
                unsigned va, vb;
                do {
                    ld_acq2(&g_flag[d][tid << 1], va, vb);
                } while (va < tgt || vb < tgt);
            }
            __syncthreads();   // S5: released once warp 0 observed all flags
        }
    }

    // ---- final states ----
    if (write_states && tid < 256) {
        const int hl = tid >> 5;
        size_t so = (size_t)16777216;  // T*B*2H
        float hfin = sHO[b * 9 + hl];
        out[so + ((size_t)d * BB + b) * HH + base + hl] = hfin;              // h_out
        out[so + 2 * BB * HH + ((size_t)d * BB + b) * HH + base + hl] = c;   // c_out
    }
}

// ============================================================
// launch
// ============================================================
extern "C" void kernel_launch(void* const* d_in, const int* in_sizes, int n_in,
                              void* d_out, int out_size)
{
    const float* x    = (const float*)d_in[0];   // [512,32,512]
    const float* h0   = (const float*)d_in[1];   // [2,32,512]
    const float* c0   = (const float*)d_in[2];   // [2,32,512]
    const float* W_ih = (const float*)d_in[3];   // [2,2048,512]
    const float* b_ih = (const float*)d_in[4];   // [2,2048]
    const float* W_hh = (const float*)d_in[5];   // [2,2048,512]
    const float* b_hh = (const float*)d_in[6];   // [2,2048]
    float* out = (float*)d_out;

    int write_states = (out_size >= 16777216 + 2 * 2 * BB * HH) ? 1 : 0;

    dim3 ggrid(GN / BN, GM / BM);   // (32, 128)
    gemm_xpre<<<ggrid, 256>>>(x, W_ih, b_ih, b_hh);

    cudaFuncSetAttribute(lstm_rec, cudaFuncAttributeMaxDynamicSharedMemorySize, REC_SMEM);
    lstm_rec<<<128, RT, REC_SMEM>>>(h0, c0, W_hh, out, write_states);
}

// round 17
// speedup vs baseline: 1.5276x; 1.5276x over previous
#include <cuda_runtime.h>
#include <cuda_bf16.h>

typedef unsigned long long ull;

// ---------------- problem constants ----------------
#define TT 512
#define BB 32
#define HH 512
#define GM 16384          // T*B
#define GN 4096           // 2 dirs * 4H
#define GK 512            // D (= H)

// ---------------- scratch ----------------
__device__ float g_xpre[(size_t)GM * GN];   // precomputed input gates (+ both biases)
// 8 arrival counters per direction, spaced 64 words (256B) to land on
// distinct LTS slices: arrival drain ~8x27cyc instead of 64x27.
__device__ unsigned int g_cnt[2][8 * 64];

// ---------------- f32x2 helpers ----------------
__device__ __forceinline__ ull pack2(float lo, float hi) {
    ull r; asm("mov.b64 %0, {%1, %2};" : "=l"(r) : "f"(lo), "f"(hi)); return r;
}
__device__ __forceinline__ void unpack2(ull v, float& lo, float& hi) {
    asm("mov.b64 {%0, %1}, %2;" : "=f"(lo), "=f"(hi) : "l"(v));
}
__device__ __forceinline__ ull fma2(ull a, ull b, ull c) {
    ull d; asm("fma.rn.f32x2 %0, %1, %2, %3;" : "=l"(d) : "l"(a), "l"(b), "l"(c)); return d;
}
__device__ __forceinline__ ull add2(ull a, ull b) {
    ull d; asm("add.rn.f32x2 %0, %1, %2;" : "=l"(d) : "l"(a), "l"(b)); return d;
}

// ---------------- fast activations ----------------
__device__ __forceinline__ float tanh_fast(float x) {
    float y; asm("tanh.approx.f32 %0, %1;" : "=f"(y) : "f"(x)); return y;
}
__device__ __forceinline__ float sigmoid_fast(float x) {
    return fmaf(tanh_fast(0.5f * x), 0.5f, 0.5f);
}

// ============================================================
// Kernel 1: x_pre GEMM.  C[m][n] = A[m][:] . W[n][:] + bih[n] + bhh[n]
// (unchanged — known good)
// ============================================================
#define BM 128
#define BN 128
#define BK 16

__global__ void __launch_bounds__(256, 2) gemm_xpre(
    const float* __restrict__ A, const float* __restrict__ W,
    const float* __restrict__ bih, const float* __restrict__ bhh)
{
    // reset barrier counters (graph replays reuse device globals)
    if (blockIdx.x == 0 && blockIdx.y == 0) {
#pragma unroll
        for (int i = 0; i < 4; i++)
            ((unsigned*)g_cnt)[threadIdx.x + (i << 8)] = 0u;
    }

    __shared__ float As[2][BK][BM];
    __shared__ float Bs[2][BK][BN];

    const int tid = threadIdx.x;
    const int m0 = blockIdx.y * BM;
    const int n0 = blockIdx.x * BN;

    const int lr = tid >> 2;           // 0..63
    const int lk = (tid & 3) << 2;     // 0,4,8,12
    const int lk4 = tid & 3;

    const float4* A4 = (const float4*)A;
    const float4* W4 = (const float4*)W;

    const int ty = tid >> 4;
    const int tx = tid & 15;

    ull acc[8][4];
#pragma unroll
    for (int i = 0; i < 8; i++)
#pragma unroll
        for (int j = 0; j < 4; j++) acc[i][j] = 0ull;

    {
        int ak = lk4;
        float4 a0 = A4[(size_t)(m0 + lr) * 128 + ak];
        float4 a1 = A4[(size_t)(m0 + lr + 64) * 128 + ak];
        float4 b0 = W4[(size_t)(n0 + lr) * 128 + ak];
        float4 b1 = W4[(size_t)(n0 + lr + 64) * 128 + ak];
        As[0][lk + 0][lr] = a0.x; As[0][lk + 1][lr] = a0.y;
        As[0][lk + 2][lr] = a0.z; As[0][lk + 3][lr] = a0.w;
        As[0][lk + 0][lr + 64] = a1.x; As[0][lk + 1][lr + 64] = a1.y;
        As[0][lk + 2][lr + 64] = a1.z; As[0][lk + 3][lr + 64] = a1.w;
        Bs[0][lk + 0][lr] = b0.x; Bs[0][lk + 1][lr] = b0.y;
        Bs[0][lk + 2][lr] = b0.z; Bs[0][lk + 3][lr] = b0.w;
        Bs[0][lk + 0][lr + 64] = b1.x; Bs[0][lk + 1][lr + 64] = b1.y;
        Bs[0][lk + 2][lr + 64] = b1.z; Bs[0][lk + 3][lr + 64] = b1.w;
    }
    __syncthreads();

    int bf = 0;
    const int NKT = GK / BK;
    float4 ra0, ra1, rb0, rb1;

    for (int kt = 0; kt < NKT; kt++) {
        if (kt < NKT - 1) {
            int ak = (kt + 1) * 4 + lk4;
            ra0 = A4[(size_t)(m0 + lr) * 128 + ak];
            ra1 = A4[(size_t)(m0 + lr + 64) * 128 + ak];
            rb0 = W4[(size_t)(n0 + lr) * 128 + ak];
            rb1 = W4[(size_t)(n0 + lr + 64) * 128 + ak];
        }
#pragma unroll
        for (int k = 0; k < BK; k++) {
            float4 a0 = *(const float4*)&As[bf][k][ty * 8];
            float4 a1 = *(const float4*)&As[bf][k][ty * 8 + 4];
            ulonglong2 bA = *(const ulonglong2*)&Bs[bf][k][tx * 8];
            ulonglong2 bB = *(const ulonglong2*)&Bs[bf][k][tx * 8 + 4];
            ull bb0 = bA.x, bb1 = bA.y, bb2 = bB.x, bb3 = bB.y;
            float av[8] = {a0.x, a0.y, a0.z, a0.w, a1.x, a1.y, a1.z, a1.w};
#pragma unroll
            for (int i = 0; i < 8; i++) {
                ull ap = pack2(av[i], av[i]);
                acc[i][0] = fma2(ap, bb0, acc[i][0]);
                acc[i][1] = fma2(ap, bb1, acc[i][1]);
                acc[i][2] = fma2(ap, bb2, acc[i][2]);
                acc[i][3] = fma2(ap, bb3, acc[i][3]);
            }
        }
        if (kt < NKT - 1) {
            int nb = bf ^ 1;
            As[nb][lk + 0][lr] = ra0.x; As[nb][lk + 1][lr] = ra0.y;
            As[nb][lk + 2][lr] = ra0.z; As[nb][lk + 3][lr] = ra0.w;
            As[nb][lk + 0][lr + 64] = ra1.x; As[nb][lk + 1][lr + 64] = ra1.y;
            As[nb][lk + 2][lr + 64] = ra1.z; As[nb][lk + 3][lr + 64] = ra1.w;
            Bs[nb][lk + 0][lr] = rb0.x; Bs[nb][lk + 1][lr] = rb0.y;
            Bs[nb][lk + 2][lr] = rb0.z; Bs[nb][lk + 3][lr] = rb0.w;
            Bs[nb][lk + 0][lr + 64] = rb1.x; Bs[nb][lk + 1][lr + 64] = rb1.y;
            Bs[nb][lk + 2][lr + 64] = rb1.z; Bs[nb][lk + 3][lr + 64] = rb1.w;
            __syncthreads();
            bf = nb;
        }
    }

    float bias[8];
#pragma unroll
    for (int j = 0; j < 8; j++) {
        int n = n0 + tx * 8 + j;
        bias[j] = bih[n] + bhh[n];
    }
#pragma unroll
    for (int i = 0; i < 8; i++) {
        size_t m = (size_t)(m0 + ty * 8 + i);
        float4 v0, v1;
        unpack2(acc[i][0], v0.x, v0.y);
        unpack2(acc[i][1], v0.z, v0.w);
        unpack2(acc[i][2], v1.x, v1.y);
        unpack2(acc[i][3], v1.z, v1.w);
        v0.x += bias[0]; v0.y += bias[1]; v0.z += bias[2]; v0.w += bias[3];
        v1.x += bias[4]; v1.y += bias[5]; v1.z += bias[6]; v1.w += bias[7];
        *(float4*)&g_xpre[m * GN + n0 + tx * 8]     = v0;
        *(float4*)&g_xpre[m * GN + n0 + tx * 8 + 4] = v1;
    }
}

// ============================================================
// Kernel 2: persistent bidirectional LSTM recurrence.
// R14 proven structure. Barrier = hierarchical atomics:
//   arrival  : tid0 atomicAdd to counter (cc>>3): 8 CTAs/counter, 8 counters
//              spaced 256B -> per-address ripple 8x27cyc, in parallel slices
//   detection: lanes 0..7 each poll their own counter (sparse traffic,
//              1 coalesced poll per CTA per ~260cyc — R14-proven density)
// Activations via tanh.approx.f32 (rel_err ~6e-6, validated R16).
// ============================================================
#define RT 512                               // threads in recurrence CTA
#define HT_P 516
#define OFF_W    0                           // 16384 floats
#define OFF_HT   16384                       // 16512 floats
#define OFF_PART (16384 + 32 * HT_P)         // 16384 floats ([32][16][32])
#define OFF_GI   (OFF_PART + 32 * 16 * 32)   // 1056 floats
#define OFF_HO   (OFF_GI + 32 * 33)          // 288 floats ([32][9])
#define REC_FLOATS (OFF_HO + 32 * 9)
#define REC_SMEM (REC_FLOATS * 4)            // ~202,496 bytes

__global__ void __launch_bounds__(RT, 1) lstm_rec(
    const float* __restrict__ h0, const float* __restrict__ c0,
    const float* __restrict__ Whh, float* __restrict__ out,
    int write_states)
{
    extern __shared__ float sm[];
    float* sW    = sm + OFF_W;      // [32][512]
    float* hT    = sm + OFF_HT;     // [32][516]
    float* sPart = sm + OFF_PART;   // [32][16][32]
    float* sGI   = sm + OFF_GI;     // [32][33]
    float* sHO   = sm + OFF_HO;     // [32][9]

    const int tid = threadIdx.x;
    const int cta = blockIdx.x;       // 0..127
    const int d = cta >> 6;           // direction
    const int cc = cta & 63;
    const int base = cc << 3;         // h index base (8 per CTA)
    const int w = tid >> 5;           // k-chunk (0..15)
    const int b = tid & 31;           // batch

    // ---- load this CTA's W_hh slice: rows r = gate*8 + hl ----
    const float4* W4 = (const float4*)Whh;
#pragma unroll
    for (int i = 0; i < 8; i++) {
        int idx = tid + i * RT;          // 0..4095
        int r = idx >> 7;
        int k4 = idx & 127;
        int grow = ((r >> 3) << 9) + base + (r & 7);     // gate*512 + base + hl
        ((float4*)sW)[r * 128 + k4] = W4[(size_t)(d * 2048 + grow) * 128 + k4];
    }

    // c carried by tid<256: thread (hl = tid>>5 in 0..7, b)
    float c = 0.f;
    if (tid < 256) c = c0[(size_t)d * BB * HH + (size_t)b * HH + base + (tid >> 5)];

    // ---- prologue: prefetch gate inputs for step 0 (coalesced) ----
    float gi[2];
    {
        int t0 = d ? (TT - 1) : 0;
#pragma unroll
        for (int i = 0; i < 2; i++) {
            int idx = tid + (i << 9);
            int bb2 = idx >> 5, g = (idx >> 3) & 3, wi = idx & 7;
            gi[i] = g_xpre[(size_t)(t0 * BB + bb2) * GN + d * 2048 + g * 512 + base + wi];
        }
    }
    __syncthreads();

    for (int s = 0; s < TT; s++) {
        const int t = d ? (TT - 1 - s) : s;

        // ---- (a) deposit prefetched gate inputs into sGI ----
#pragma unroll
        for (int i = 0; i < 2; i++) {
            int idx = tid + (i << 9);
            int bb2 = idx >> 5, g = (idx >> 3) & 3, wi = idx & 7;
            sGI[bb2 * 33 + g * 8 + wi] = gi[i];
        }

        // ---- (b) stage previous h into hT (coalesced LDG + conflict-free STS) ----
        {
            const float* hsrc;
            int hstr4;
            if (s == 0) { hsrc = h0 + (size_t)d * BB * HH; hstr4 = HH >> 2; }
            else {
                int tp = d ? (t + 1) : (t - 1);
                hsrc = out + (size_t)tp * BB * 1024 + d * HH;
                hstr4 = 1024 >> 2;
            }
            const float4* s4 = (const float4*)hsrc;
#pragma unroll
            for (int i = 0; i < 8; i++) {
                int idx = tid + (i << 9);       // 0..4095
                int bb2 = idx >> 7;             // batch row
                int kq  = idx & 127;            // float4 within row
                float4 v = s4[(size_t)bb2 * hstr4 + kq];
                *(float4*)&hT[bb2 * HT_P + (kq << 2)] = v;
            }
        }

        // ---- (c) prefetch gate inputs for NEXT step ----
        if (s < TT - 1) {
            int tn = d ? (TT - 2 - s) : (s + 1);
#pragma unroll
            for (int i = 0; i < 2; i++) {
                int idx = tid + (i << 9);
                int bb2 = idx >> 5, g = (idx >> 3) & 3, wi = idx & 7;
                gi[i] = g_xpre[(size_t)(tn * BB + bb2) * GN + d * 2048 + g * 512 + base + wi];
            }
        }
        __syncthreads();   // S1

        // ---- (e) compute: 32-float k-chunk per thread ----
        ulonglong2 h2[8];
        {
            const ulonglong2* hp = (const ulonglong2*)&hT[b * HT_P + (w << 5)];
#pragma unroll
            for (int q = 0; q < 8; q++) h2[q] = hp[q];
        }

#pragma unroll 2
        for (int j = 0; j < 32; j++) {
            const ulonglong2* wp = (const ulonglong2*)(sW + j * 512 + (w << 5));
            ull a0 = 0, a1 = 0, a2 = 0, a3 = 0;
#pragma unroll
            for (int q = 0; q < 8; q += 2) {
                ulonglong2 wv0 = wp[q];
                ulonglong2 wv1 = wp[q + 1];
                a0 = fma2(wv0.x, h2[q].x, a0);
                a1 = fma2(wv0.y, h2[q].y, a1);
                a2 = fma2(wv1.x, h2[q + 1].x, a2);
                a3 = fma2(wv1.y, h2[q + 1].y, a3);
            }
            ull aa = add2(add2(a0, a1), add2(a2, a3));
            float lo, hi;
            unpack2(aa, lo, hi);
            sPart[(j << 9) + (w << 5) + b] = lo + hi;
        }
        __syncthreads();   // S2

        // ---- (g) update phase: tid<256, thread (hl, b) ----
        if (tid < 256) {
            const int hl = tid >> 5;
            float g4[4];
#pragma unroll
            for (int g = 0; g < 4; g++) {
                int j = g * 8 + hl;
                const float* pp = sPart + (j << 9) + b;
                float s0 = 0.f, s1 = 0.f, s2 = 0.f, s3 = 0.f;
#pragma unroll
                for (int q = 0; q < 16; q += 4) {
                    s0 += pp[(q + 0) << 5];
                    s1 += pp[(q + 1) << 5];
                    s2 += pp[(q + 2) << 5];
                    s3 += pp[(q + 3) << 5];
                }
                g4[g] = (s0 + s1) + (s2 + s3) + sGI[b * 33 + g * 8 + hl];
            }

            float ig = sigmoid_fast(g4[0]);
            float fg = sigmoid_fast(g4[1]);
            float gg = tanh_fast(g4[2]);
            float og = sigmoid_fast(g4[3]);
            c = fg * c + ig * gg;
            float h = og * tanh_fast(c);
            sHO[b * 9 + hl] = h;
        }
        __syncthreads();   // S3

        // ---- (j) coalesced h writeback (tid<256) ----
        if (tid < 256) {
            int bb2 = tid >> 3, wi = tid & 7;
            out[(size_t)t * BB * 1024 + (size_t)bb2 * 1024 + d * HH + base + wi] =
                sHO[bb2 * 9 + wi];
        }

        // ---- (k) hierarchical atomic grid barrier (per direction) ----
        if (s < TT - 1) {
            __syncthreads();   // S4: all writeback STGs done (program order) before release
            if (tid == 0) {
                __threadfence();
                atomicAdd(&g_cnt[d][(cc >> 3) << 6], 1u);
            }
            if (tid < 8) {
                const unsigned tgt = (unsigned)(s + 1) * 8u;
                while (*(volatile unsigned*)&g_cnt[d][tid << 6] < tgt) { }
                __threadfence();
            }
            __syncthreads();   // S5
        }
    }

    // ---- final states ----
    if (write_states && tid < 256) {
        const int hl = tid >> 5;
        size_t so = (size_t)16777216;  // T*B*2H
        float hfin = sHO[b * 9 + hl];
        out[so + ((size_t)d * BB + b) * HH + base + hl] = hfin;              // h_out
        out[so + 2 * BB * HH + ((size_t)d * BB + b) * HH + base + hl] = c;   // c_out
    }
}

// ============================================================
// launch
// ============================================================
extern "C" void kernel_launch(void* const* d_in, const int* in_sizes, int n_in,
                              void* d_out, int out_size)
{
    const float* x    = (const float*)d_in[0];   // [512,32,512]
    const float* h0   = (const float*)d_in[1];   // [2,32,512]
    const float* c0   = (const float*)d_in[2];   // [2,32,512]
    const float* W_ih = (const float*)d_in[3];   // [2,2048,512]
    const float* b_ih = (const float*)d_in[4];   // [2,2048]
    const float* W_hh = (const float*)d_in[5];   // [2,2048,512]
    const float* b_hh = (const float*)d_in[6];   // [2,2048]
    float* out = (float*)d_out;

    int write_states = (out_size >= 16777216 + 2 * 2 * BB * HH) ? 1 : 0;

    dim3 ggrid(GN / BN, GM / BM);   // (32, 128)
    gemm_xpre<<<ggrid, 256>>>(x, W_ih, b_ih, b_hh);

    cudaFuncSetAttribute(lstm_rec, cudaFuncAttributeMaxDynamicSharedMemorySize, REC_SMEM);
    lstm_rec<<<128, RT, REC_SMEM>>>(h0, c0, W_hh, out, write_states);
}